// round 9
// baseline (speedup 1.0000x reference)
#include <cuda_runtime.h>
#include <stdint.h>

// ---------------------------------------------------------------------------
// DownsampleWithPruning — sparse stride-2 conv (2x2x2) + prune by ref set.
// Keyspace: b<<24 | x<<16 | y<<8 | z  in [0, 2^26)
//
// DAG:
//   s0: k_fill_tma  260MB zeros via TMA bulk stores (no LSU/issue footprint)
//   sB: k_ref -> k_main (parent bitmap + per-(tap,block) lists, coords read 1x)
//       -> k_scanemit (dual lookback: coords + rankBase + masked list)
//   s0: join -> k_biasconv (pad + mask/bias + conv scatter atomics)
// ---------------------------------------------------------------------------

#define WORDS   (1 << 20)       // 2^26 keys / 64
#define NCHUNK  1024            // scan chunks
#define CWORDS  1024            // bitmap words per chunk
#define MASK21  0x1FFFFFull
#define FCH     1024            // items per k_main block
#define FBLKMAX 1024
#define LCAP    64

__device__ unsigned long long g_bitmap[WORDS];   // parent-key occupancy (8MB)
__device__ unsigned long long g_refbit[WORDS];   // ref-key occupancy (8MB)
__device__ unsigned long long g_state[NCHUNK];   // flag<<62 | rank<<21 | mask
__device__ int g_rankBase[WORDS];
__device__ int g_masked[1 << 20];                // ranks of masked outputs
__device__ int g_M;
__device__ int g_mTotal;
__device__ int g_cntS[8][FBLKMAX];               // per-(tap,block) counts
__device__ int g_listS[8][FBLKMAX][LCAP];        // per-(tap,block) input idx
__device__ int g_ovfl[8192];
__device__ int g_ovflCnt;

// ---- TMA bulk-store zero fill ------------------------------------------------
#define CHB 32768
#define CHF (CHB / 4)

__global__ void __launch_bounds__(128) k_fill_tma(float* __restrict__ out,
                                                  long long startFloat,
                                                  long long numFloats) {
    __shared__ __align__(128) float sbuf[CHF];
    for (int i = threadIdx.x; i < CHF; i += 128) sbuf[i] = 0.0f;
    __syncthreads();
    long long nch = (numFloats * 4) / CHB;
    if (threadIdx.x == 0) {
        asm volatile("fence.proxy.async.shared::cta;" ::: "memory");
        uint32_t saddr;
        asm("{ .reg .u64 t; cvta.to.shared.u64 t, %1; cvt.u32.u64 %0, t; }"
            : "=r"(saddr) : "l"(sbuf));
        char* base = (char*)(out + startFloat);
        int chb = CHB;
        for (long long c = blockIdx.x; c < nch; c += gridDim.x)
            asm volatile("cp.async.bulk.global.shared::cta.bulk_group [%0], [%1], %2;"
                         :: "l"(base + c * CHB), "r"(saddr), "r"(chb) : "memory");
        asm volatile("cp.async.bulk.commit_group;" ::: "memory");
        asm volatile("cp.async.bulk.wait_group 0;" ::: "memory");
    }
    long long done = nch * CHF;
    if (blockIdx.x == 0)
        for (long long t = done + threadIdx.x; t < numFloats; t += 128)
            out[startFloat + t] = 0.0f;
}

// ---- ref bitmap + resets ------------------------------------------------------
__global__ void __launch_bounds__(256) k_ref(const int* __restrict__ rc, int NR) {
    int tid = blockIdx.x * blockDim.x + threadIdx.x;
    if (tid < NCHUNK) g_state[tid] = 0ull;
    if (tid == 0) g_ovflCnt = 0;
    if (tid >= NR) return;
    int4 c = ((const int4*)rc)[tid];
    int key = (c.x << 24) | (c.y << 16) | (c.z << 8) | c.w;
    atomicOr(&g_refbit[key >> 6], 1ull << (key & 63));
}

// ---- main pass: parent bitmap + per-(tap,block) lists (coords read once) -----
__global__ void __launch_bounds__(256) k_main(const int* __restrict__ coords, int N) {
    __shared__ int s_cnt[8];
    int tid = threadIdx.x, b = blockIdx.x;
    if (tid < 8) s_cnt[tid] = 0;
    __syncthreads();
    int base = b * FCH;
    const int4* c4 = (const int4*)coords;
#pragma unroll
    for (int r = 0; r < FCH / 256; r++) {
        int i = base + r * 256 + tid;
        if (i < N) {
            int4 c = c4[i];
            int key  = (c.x << 24) | (c.y << 16) | (c.z << 8) | c.w;
            int pkey = key & ~0x00010101;
            atomicOr(&g_bitmap[pkey >> 6], 1ull << (pkey & 63));
            if ((g_refbit[pkey >> 6] >> (pkey & 63)) & 1ull) {
                int tap = ((key >> 14) & 4) | ((key >> 7) & 2) | (key & 1);
                int lp = atomicAdd(&s_cnt[tap], 1);
                if (lp < LCAP) g_listS[tap][b][lp] = i;
                else {
                    int op = atomicAdd(&g_ovflCnt, 1);
                    if (op < 8192) g_ovfl[op] = (tap << 28) | i;
                }
            }
        }
    }
    __syncthreads();
    if (tid < 8) g_cntS[tid][b] = s_cnt[tid] < LCAP ? s_cnt[tid] : LCAP;
}

// ---- single-pass dual-value lookback scan + emit -----------------------------
__global__ void __launch_bounds__(256) k_scanemit(float* __restrict__ out) {
    __shared__ unsigned long long sh[256];
    __shared__ int s_exR, s_exM;
    int tid = threadIdx.x, c = blockIdx.x;

    int base = c * CWORDS + tid * 4;
    unsigned long long w[4], mw[4];
    int s = 0, m = 0;
#pragma unroll
    for (int j = 0; j < 4; j++) {
        w[j]  = g_bitmap[base + j];
        mw[j] = w[j] & g_refbit[base + j];
        s += __popcll(w[j]);
        m += __popcll(mw[j]);
    }
    sh[tid] = ((unsigned long long)s << 32) | (unsigned)m;
    __syncthreads();
    for (int off = 1; off < 256; off <<= 1) {
        unsigned long long t = (tid >= off) ? sh[tid - off] : 0ull;
        __syncthreads();
        sh[tid] += t;
        __syncthreads();
    }
    int thrExR = (int)(sh[tid] >> 32) - s;
    int thrExM = (int)(sh[tid] & 0xFFFFFFFFull) - m;
    int aggR = (int)(sh[255] >> 32);
    int aggM = (int)(sh[255] & 0xFFFFFFFFull);

    if (tid == 0) {
        long long exR = 0, exM = 0;
        if (c == 0) {
            atomicExch(&g_state[0], (2ull << 62) |
                       ((unsigned long long)aggR << 21) | (unsigned long long)aggM);
        } else {
            atomicExch(&g_state[c], (1ull << 62) |
                       ((unsigned long long)aggR << 21) | (unsigned long long)aggM);
            int j = c - 1;
            while (true) {
                unsigned long long v = *((volatile unsigned long long*)&g_state[j]);
                unsigned f = (unsigned)(v >> 62);
                if (f == 0) continue;
                exR += (long long)((v >> 21) & MASK21);
                exM += (long long)(v & MASK21);
                if (f == 2) break;
                j--;
            }
            atomicExch(&g_state[c], (2ull << 62) |
                       ((unsigned long long)(exR + aggR) << 21) |
                       (unsigned long long)(exM + aggM));
        }
        s_exR = (int)exR;
        s_exM = (int)exM;
        if (c == NCHUNK - 1) { g_M = (int)exR + aggR; g_mTotal = (int)exM + aggM; }
    }
    __syncthreads();

    int rank  = s_exR + thrExR;
    int mrank = s_exM + thrExM;
#pragma unroll
    for (int j = 0; j < 4; j++) {
        g_rankBase[base + j] = rank;
        unsigned long long ww = w[j];
        unsigned long long mm = mw[j];
        int keyhi = (base + j) << 6;
        while (ww) {
            int bpos = __ffsll((long long)ww) - 1;
            ww &= ww - 1;
            int k = keyhi | bpos;
            ((float4*)out)[rank] = make_float4((float)(k >> 24),
                                               (float)((k >> 16) & 255),
                                               (float)((k >> 8) & 255),
                                               (float)(k & 255));
            if ((mm >> bpos) & 1ull) g_masked[mrank++] = rank;
            rank++;
        }
    }
}

// ---- pad coords + mask=1 + bias + conv scatter -------------------------------
__global__ void __launch_bounds__(256) k_biasconv(const float* __restrict__ feats,
                                                  const float* __restrict__ W,
                                                  const int* __restrict__ coords,
                                                  const float* __restrict__ bias,
                                                  float* __restrict__ out,
                                                  int N, int FBLK,
                                                  long long featBase,
                                                  long long maskBase) {
    int lane = threadIdx.x & 31;
    int gtid = blockIdx.x * blockDim.x + threadIdx.x;
    int Tthr = gridDim.x * blockDim.x;
    int gw   = gtid >> 5;
    int totalWarps = Tthr >> 5;
    const int4* c4 = (const int4*)coords;

    int M = g_M;
    float4 neg1 = make_float4(-1.f, -1.f, -1.f, -1.f);
    for (int r = M + gtid; r < N; r += Tthr) ((float4*)out)[r] = neg1;

    float bv0 = __ldg(&bias[lane]);
    float bv1 = __ldg(&bias[32 + lane]);
    int mc = g_mTotal;
    for (int i = gw; i < mc; i += totalWarps) {
        int r = g_masked[i];
        if (lane == 0) out[maskBase + r] = 1.0f;
        float* dst = out + featBase + (long long)r * 64;
        atomicAdd(dst + lane, bv0);
        atomicAdd(dst + 32 + lane, bv1);
    }

    for (int job = gw; job < 16 * FBLK; job += totalWarps) {
        int tap   = job & 7;
        int half  = (job >> 3) & 1;
        int slice = job >> 4;
        int cnt = g_cntS[tap][slice];
        if (cnt == 0) continue;
        float wreg[32];
        const float* Wt = W + tap * 2048 + half * 32 + lane;
#pragma unroll
        for (int j = 0; j < 32; j++) wreg[j] = __ldg(&Wt[j * 64]);
        for (int k = 0; k < cnt; k++) {
            int n = g_listS[tap][slice][k];
            int4 c = c4[n];
            int pkey = ((c.x << 24) | (c.y << 16) | (c.z << 8) | c.w) & ~0x00010101;
            int word = pkey >> 6, bit = pkey & 63;
            int rank = g_rankBase[word] +
                       __popcll(g_bitmap[word] & ((1ull << bit) - 1ull));
            float f = __ldg(&feats[(long long)n * 32 + lane]);
            float a = 0.f;
#pragma unroll
            for (int j = 0; j < 32; j++)
                a += __shfl_sync(0xffffffffu, f, j) * wreg[j];
            atomicAdd(out + featBase + (long long)rank * 64 + half * 32 + lane, a);
        }
    }

    int oc = g_ovflCnt;
    for (int e = gw; e < oc && e < 8192; e += totalWarps) {
        int v = g_ovfl[e];
        int tap = v >> 28, n = v & 0x0FFFFFFF;
        int4 c = c4[n];
        int pkey = ((c.x << 24) | (c.y << 16) | (c.z << 8) | c.w) & ~0x00010101;
        int word = pkey >> 6, bit = pkey & 63;
        int rank = g_rankBase[word] +
                   __popcll(g_bitmap[word] & ((1ull << bit) - 1ull));
        float f = __ldg(&feats[(long long)n * 32 + lane]);
        for (int half = 0; half < 2; half++) {
            float a = 0.f;
            for (int j = 0; j < 32; j++)
                a += __shfl_sync(0xffffffffu, f, j) *
                     __ldg(&W[tap * 2048 + j * 64 + half * 32 + lane]);
            atomicAdd(out + featBase + (long long)rank * 64 + half * 32 + lane, a);
        }
    }
}

// ---- streams/events created at load time (no device-memory allocation) -----
static cudaStream_t g_sB;
static cudaEvent_t  g_evFork, g_evEmit;
namespace {
struct ResInit {
    ResInit() {
        cudaStreamCreateWithFlags(&g_sB, cudaStreamNonBlocking);
        cudaEventCreateWithFlags(&g_evFork, cudaEventDisableTiming);
        cudaEventCreateWithFlags(&g_evEmit, cudaEventDisableTiming);
    }
};
static ResInit g_resInit;
}

extern "C" void kernel_launch(void* const* d_in, const int* in_sizes, int n_in,
                              void* d_out, int out_size) {
    const float* feats  = (const float*)d_in[0];
    const float* W      = (const float*)d_in[1];
    const float* bias   = (const float*)d_in[2];
    const int*   coords = (const int*)d_in[3];
    const int*   ref    = (const int*)d_in[4];
    float* out = (float*)d_out;

    int N  = in_sizes[3] / 4;
    int NR = in_sizes[4] / 4;
    int FBLK = (N + FCH - 1) / FCH;
    long long featBase = 4LL * N;
    long long maskBase = (long long)out_size - N;          // == 68N
    long long zeroLen  = (long long)out_size - featBase;   // feats + mask (65N)

    cudaEventRecord(g_evFork, 0);
    cudaStreamWaitEvent(g_sB, g_evFork, 0);

    // s0: 260MB zero fill via TMA engines (minimal SM footprint)
    k_fill_tma<<<296, 128, 0, 0>>>(out, featBase, zeroLen);

    // sB: ref -> main (bitmap + lists) -> scanemit
    k_ref<<<(NR + 255) / 256, 256, 0, g_sB>>>(ref, NR);
    k_main<<<FBLK, 256, 0, g_sB>>>(coords, N);
    k_scanemit<<<NCHUNK, 256, 0, g_sB>>>(out);
    cudaEventRecord(g_evEmit, g_sB);

    // join on s0: biasconv after fill + chain
    cudaStreamWaitEvent(0, g_evEmit, 0);
    k_biasconv<<<1184, 256, 0, 0>>>(feats, W, coords, bias, out,
                                    N, FBLK, featBase, maskBase);
}